// round 1
// baseline (speedup 1.0000x reference)
#include <cuda_runtime.h>
#include <math.h>

// Problem constants
#define NN_ 64
#define PP_ 1024
#define EE_ 512
#define HH_ 8
#define RR_ 64
#define MBIG (NN_ * PP_)   // 65536

// Scratch (allocation-free rule: __device__ globals)
__device__ float g_ws[(size_t)NN_ * PP_ * EE_];  // 128 MB: ws[n,p,h*R+r]
__device__ float g_y [(size_t)NN_ * PP_ * EE_];  // 128 MB: y [n,p,h*R+r]

__device__ __forceinline__ float log_cosh_f(float v) {
    float ax = fabsf(v);
    return ax + log1pf(expf(-2.0f * ax)) - 0.6931471805599453f;
}

// ---------------------------------------------------------------------------
// GEMM NT: C[m,n] = sum_k A[m,k] * B[n,k]
// A: (M,K) row-major, B: (N,K) row-major. 64x64 block tile, BK=16,
// 256 threads, 4x4 microtile. M,N % 64 == 0, K % 16 == 0.
// ---------------------------------------------------------------------------
__global__ __launch_bounds__(256)
void gemm_nt_kernel(const float* __restrict__ A, const float* __restrict__ B,
                    float* __restrict__ C, int M, int Nc, int K)
{
    __shared__ float As[16][68];
    __shared__ float Bs[16][68];

    const int tid = threadIdx.x;
    const int tx  = tid & 15;        // 0..15 (n dir)
    const int ty  = tid >> 4;        // 0..15 (m dir)
    const int bm  = blockIdx.y * 64;
    const int bn  = blockIdx.x * 64;

    const int lrow = tid >> 2;       // 0..63
    const int lk   = (tid & 3) * 4;  // 0,4,8,12

    const float* Ap = A + (size_t)(bm + lrow) * K + lk;
    const float* Bp = B + (size_t)(bn + lrow) * K + lk;

    float acc[4][4] = {};

    for (int k0 = 0; k0 < K; k0 += 16) {
        float4 av = *(const float4*)(Ap + k0);
        float4 bv = *(const float4*)(Bp + k0);
        __syncthreads();
        As[lk + 0][lrow] = av.x; As[lk + 1][lrow] = av.y;
        As[lk + 2][lrow] = av.z; As[lk + 3][lrow] = av.w;
        Bs[lk + 0][lrow] = bv.x; Bs[lk + 1][lrow] = bv.y;
        Bs[lk + 2][lrow] = bv.z; Bs[lk + 3][lrow] = bv.w;
        __syncthreads();

        #pragma unroll
        for (int k = 0; k < 16; k++) {
            float4 a4 = *(const float4*)&As[k][ty * 4];
            float4 b4 = *(const float4*)&Bs[k][tx * 4];
            float a[4] = {a4.x, a4.y, a4.z, a4.w};
            float b[4] = {b4.x, b4.y, b4.z, b4.w};
            #pragma unroll
            for (int i = 0; i < 4; i++)
                #pragma unroll
                for (int j = 0; j < 4; j++)
                    acc[i][j] += a[i] * b[j];
        }
    }

    float* Cp = C + (size_t)(bm + ty * 4) * Nc + bn + tx * 4;
    #pragma unroll
    for (int i = 0; i < 4; i++) {
        float4 o = make_float4(acc[i][0], acc[i][1], acc[i][2], acc[i][3]);
        *(float4*)(Cp + (size_t)i * Nc) = o;
    }
}

// ---------------------------------------------------------------------------
// Circulant stage: y[n, p, h*R + r] = sum_j alpha[h, (j - p) & 1023] * ws[n, j, h*R + r]
// Block: 64 p-rows x 64 r-cols for one (n, h). Grid (P/64, H, N).
// alpha row cached in smem; per k-tile the 19 needed alpha values are
// hoisted into registers so the inner loop is pure FFMA + 1 LDS.128.
// ---------------------------------------------------------------------------
__global__ __launch_bounds__(256)
void circulant_kernel(const float* __restrict__ alpha)
{
    const int n  = blockIdx.z;
    const int h  = blockIdx.y;
    const int bp = blockIdx.x * 64;

    __shared__ float alpha_s[1024];
    __shared__ float Bs[16][68];

    const int tid = threadIdx.x;
    for (int i = tid; i < 1024; i += 256)
        alpha_s[i] = alpha[h * 1024 + i];

    const int tx = tid & 15;
    const int ty = tid >> 4;
    const int brow = tid >> 4;        // 0..15 (j within tile)
    const int bcol = (tid & 15) * 4;  // 0..60 (r)

    const float* wsn = g_ws + (size_t)n * PP_ * EE_ + h * RR_;
    const int pbase = bp + ty * 4;

    float acc[4][4] = {};

    for (int j0 = 0; j0 < PP_; j0 += 16) {
        float4 bv = *(const float4*)(wsn + (size_t)(j0 + brow) * EE_ + bcol);
        __syncthreads();
        *(float4*)&Bs[brow][bcol] = bv;
        __syncthreads();

        // alpha values needed: index (j0 + k - pbase - i) & 1023,
        // k in [0,16), i in [0,4)  ->  t = k - i + 3 in [0,19)
        float av[19];
        #pragma unroll
        for (int t = 0; t < 19; t++)
            av[t] = alpha_s[(j0 + t - 3 - pbase) & 1023];

        #pragma unroll
        for (int k = 0; k < 16; k++) {
            float4 b4 = *(const float4*)&Bs[k][tx * 4];
            float b[4] = {b4.x, b4.y, b4.z, b4.w};
            #pragma unroll
            for (int i = 0; i < 4; i++) {
                float a = av[k - i + 3];
                acc[i][0] += a * b[0];
                acc[i][1] += a * b[1];
                acc[i][2] += a * b[2];
                acc[i][3] += a * b[3];
            }
        }
    }

    float* yp = g_y + ((size_t)n * PP_ + pbase) * EE_ + h * RR_ + tx * 4;
    #pragma unroll
    for (int i = 0; i < 4; i++) {
        float4 o = make_float4(acc[i][0], acc[i][1], acc[i][2], acc[i][3]);
        *(float4*)(yp + (size_t)i * EE_) = o;
    }
}

// ---------------------------------------------------------------------------
// GEMM NN + bias + log_cosh epilogue:
// out[m,n] = log_cosh( sum_k A[m,k] * B[k,n] + bias[n] )
// A: (M,K) row-major, B: (K,N) row-major.
// ---------------------------------------------------------------------------
__global__ __launch_bounds__(256)
void gemm_nn_logcosh_kernel(const float* __restrict__ A, const float* __restrict__ B,
                            const float* __restrict__ bias, float* __restrict__ C,
                            int M, int Nc, int K)
{
    __shared__ float As[16][68];
    __shared__ float Bs[16][68];

    const int tid = threadIdx.x;
    const int tx  = tid & 15;
    const int ty  = tid >> 4;
    const int bm  = blockIdx.y * 64;
    const int bn  = blockIdx.x * 64;

    const int arow = tid >> 2;        // 0..63
    const int ak   = (tid & 3) * 4;   // 0,4,8,12
    const int brow = tid >> 4;        // 0..15
    const int bcol = (tid & 15) * 4;  // 0..60

    const float* Ap = A + (size_t)(bm + arow) * K + ak;
    const float* Bp = B + (size_t)brow * Nc + bn + bcol;

    float acc[4][4] = {};

    for (int k0 = 0; k0 < K; k0 += 16) {
        float4 av = *(const float4*)(Ap + k0);
        float4 bv = *(const float4*)(Bp + (size_t)k0 * Nc);
        __syncthreads();
        As[ak + 0][arow] = av.x; As[ak + 1][arow] = av.y;
        As[ak + 2][arow] = av.z; As[ak + 3][arow] = av.w;
        *(float4*)&Bs[brow][bcol] = bv;
        __syncthreads();

        #pragma unroll
        for (int k = 0; k < 16; k++) {
            float4 a4 = *(const float4*)&As[k][ty * 4];
            float4 b4 = *(const float4*)&Bs[k][tx * 4];
            float a[4] = {a4.x, a4.y, a4.z, a4.w};
            float b[4] = {b4.x, b4.y, b4.z, b4.w};
            #pragma unroll
            for (int i = 0; i < 4; i++)
                #pragma unroll
                for (int j = 0; j < 4; j++)
                    acc[i][j] += a[i] * b[j];
        }
    }

    float bj[4];
    #pragma unroll
    for (int j = 0; j < 4; j++)
        bj[j] = bias[bn + tx * 4 + j];

    float* Cp = C + (size_t)(bm + ty * 4) * Nc + bn + tx * 4;
    #pragma unroll
    for (int i = 0; i < 4; i++) {
        float4 o;
        o.x = log_cosh_f(acc[i][0] + bj[0]);
        o.y = log_cosh_f(acc[i][1] + bj[1]);
        o.z = log_cosh_f(acc[i][2] + bj[2]);
        o.w = log_cosh_f(acc[i][3] + bj[3]);
        *(float4*)(Cp + (size_t)i * Nc) = o;
    }
}

// ---------------------------------------------------------------------------
extern "C" void kernel_launch(void* const* d_in, const int* in_sizes, int n_in,
                              void* d_out, int out_size)
{
    const float* x     = (const float*)d_in[0];  // (N,P,E)
    const float* alpha = (const float*)d_in[1];  // (H,P)
    const float* V     = (const float*)d_in[2];  // (H,R,E) == (H*R, E) rows K-contig
    const float* W     = (const float*)d_in[3];  // (E,E) row-major
    const float* b     = (const float*)d_in[4];  // (E,)
    float* out = (float*)d_out;                  // (N,P,E)

    void* wsp = nullptr;
    void* yp  = nullptr;
    cudaGetSymbolAddress(&wsp, g_ws);
    cudaGetSymbolAddress(&yp,  g_y);

    // Stage 1: ws = x @ V^T   (M=65536, N=512, K=512)
    gemm_nt_kernel<<<dim3(EE_ / 64, MBIG / 64), 256>>>(
        x, V, (float*)wsp, MBIG, EE_, EE_);

    // Stage 2: circulant mixing along P, per (n, h)
    circulant_kernel<<<dim3(PP_ / 64, HH_, NN_), 256>>>(alpha);

    // Stage 3: out = log_cosh(y @ W + b)   (M=65536, N=512, K=512)
    gemm_nn_logcosh_kernel<<<dim3(EE_ / 64, MBIG / 64), 256>>>(
        (float*)yp, W, b, out, MBIG, EE_, EE_);
}

// round 3
// speedup vs baseline: 3.1418x; 3.1418x over previous
#include <cuda_runtime.h>
#include <cstdint>
#include <math.h>

#define NN_ 64
#define PP_ 1024
#define EE_ 512
#define HH_ 8
#define MBIG (NN_*PP_)   // 65536

#define SA 36   // smem row stride (floats) for A tile (128 x 32)
#define SB 36   // smem row stride (floats) for B tile (64 x 32)
// dynamic smem: 2*128*SA + 2*64*SB floats = 13824 floats = 55296 B
#define SMEM_BYTES 55296

// ---------------- scratch (__device__ globals; no allocs allowed) ----------
__device__ float g_xr  [(size_t)MBIG*EE_];        // x rounded to tf32        128MB
__device__ float g_vr  [(size_t)EE_*EE_];         // V rounded (hr,d)           1MB
__device__ float g_wt  [(size_t)EE_*EE_];         // W^T rounded                1MB
__device__ float g_amat[(size_t)HH_*PP_*PP_];     // alpha_mat rounded         32MB
__device__ float g_ws2 [(size_t)NN_*EE_*PP_];     // ws transposed [n][hr][p] 128MB
__device__ float g_yr  [(size_t)NN_*PP_*EE_];     // y rounded [n][p][hr]     128MB

// ---------------- helpers --------------------------------------------------
__device__ __forceinline__ uint32_t smem_u32(const void* p){
    uint32_t a;
    asm("{ .reg .u64 t; cvta.to.shared.u64 t, %1; cvt.u32.u64 %0, t; }":"=r"(a):"l"(p));
    return a;
}
__device__ __forceinline__ float rnd_tf32(float x){
    uint32_t u; asm("cvt.rna.tf32.f32 %0, %1;":"=r"(u):"f"(x));
    return __uint_as_float(u);
}
__device__ __forceinline__ float log_cosh_f(float v){
    float ax = fabsf(v);
    return ax + log1pf(expf(-2.0f*ax)) - 0.6931471805599453f;
}
__device__ __forceinline__ void mma_tf32(float c[4],
    uint32_t a0, uint32_t a1, uint32_t a2, uint32_t a3, uint32_t b0, uint32_t b1)
{
    asm volatile("mma.sync.aligned.m16n8k8.row.col.f32.tf32.tf32.f32 "
        "{%0,%1,%2,%3}, {%4,%5,%6,%7}, {%8,%9}, {%0,%1,%2,%3};"
        : "+f"(c[0]), "+f"(c[1]), "+f"(c[2]), "+f"(c[3])
        : "r"(a0), "r"(a1), "r"(a2), "r"(a3), "r"(b0), "r"(b1));
}

// ---------------------------------------------------------------------------
// Mainloop: acc(128x64 block; per-warp 32x32) += A(128xK) * B(64xK)^T
// A,B K-major fp32 (pre-rounded to tf32). BK=32, double-buffered cp.async.
// 256 threads, warp grid 4(M) x 2(N). m16n8k8 tf32 MMAs.
// ---------------------------------------------------------------------------
__device__ __forceinline__ void gemm_loop(
    const float* __restrict__ A, int lda,
    const float* __restrict__ B, int ldb,
    int kt, float* __restrict__ sm, float acc[2][4][4])
{
    float* sA = sm;                    // 2 * 128 * SA
    float* sB = sm + 2*128*SA;         // 2 * 64  * SB
    const int tid = threadIdx.x, wid = tid >> 5, lane = tid & 31;
    const int wm = (wid >> 1) * 32, wn = (wid & 1) * 32;
    const int g = lane >> 2, t = lane & 3;

    auto load_tile = [&](int tt, int buf){
        float* dA = sA + buf*128*SA;
        float* dB = sB + buf*64*SB;
        const float* Ab = A + tt*32;
        const float* Bb = B + tt*32;
        #pragma unroll
        for (int i = 0; i < 4; i++) {                 // A: 128 rows x 8 float4
            int c = tid + i*256, row = c >> 3, seg = c & 7;
            uint32_t dst = smem_u32(dA + row*SA + seg*4);
            asm volatile("cp.async.cg.shared.global [%0], [%1], 16;"
                         :: "r"(dst), "l"(Ab + (size_t)row*lda + seg*4));
        }
        #pragma unroll
        for (int i = 0; i < 2; i++) {                 // B: 64 rows x 8 float4
            int c = tid + i*256, row = c >> 3, seg = c & 7;
            uint32_t dst = smem_u32(dB + row*SB + seg*4);
            asm volatile("cp.async.cg.shared.global [%0], [%1], 16;"
                         :: "r"(dst), "l"(Bb + (size_t)row*ldb + seg*4));
        }
        asm volatile("cp.async.commit_group;" ::: "memory");
    };

    load_tile(0, 0);

    for (int tt = 0; tt < kt; tt++) {
        const int cur = tt & 1;
        if (tt + 1 < kt) {
            load_tile(tt + 1, cur ^ 1);
            asm volatile("cp.async.wait_group 1;" ::: "memory");
        } else {
            asm volatile("cp.async.wait_group 0;" ::: "memory");
        }
        __syncthreads();

        const float* cA = sA + cur*128*SA;
        const float* cB = sB + cur*64*SB;
        #pragma unroll
        for (int ks = 0; ks < 4; ks++) {
            const int k0 = ks * 8;
            uint32_t af[2][4], bf[4][2];
            #pragma unroll
            for (int tm = 0; tm < 2; tm++) {
                const float* ap = cA + (wm + tm*16 + g)*SA + k0 + t;
                af[tm][0] = __float_as_uint(ap[0]);
                af[tm][1] = __float_as_uint(ap[8*SA]);
                af[tm][2] = __float_as_uint(ap[4]);
                af[tm][3] = __float_as_uint(ap[8*SA + 4]);
            }
            #pragma unroll
            for (int tn = 0; tn < 4; tn++) {
                const float* bp = cB + (wn + tn*8 + g)*SB + k0 + t;
                bf[tn][0] = __float_as_uint(bp[0]);
                bf[tn][1] = __float_as_uint(bp[4]);
            }
            #pragma unroll
            for (int tm = 0; tm < 2; tm++)
                #pragma unroll
                for (int tn = 0; tn < 4; tn++)
                    mma_tf32(acc[tm][tn], af[tm][0], af[tm][1], af[tm][2], af[tm][3],
                             bf[tn][0], bf[tn][1]);
        }
        __syncthreads();
    }
}

// ---------------------------------------------------------------------------
// Stage 1: ws2[n][hr][p] = rnd( sum_d x[n,p,d] * V[hr,d] )  (transposed store)
// grid (x: 8 hr-tiles of 64, y: 512 m-tiles of 128)
// ---------------------------------------------------------------------------
__global__ __launch_bounds__(256) void k_stage1()
{
    extern __shared__ float sm[];
    const int bn = blockIdx.x * 64;
    const int bm = blockIdx.y * 128;
    float acc[2][4][4] = {};
    gemm_loop(g_xr + (size_t)bm*EE_, EE_, g_vr + (size_t)bn*EE_, EE_, EE_/32, sm, acc);

    // stage C (128m x 64n) transposed into smem: Ts[n][m], stride 132
    __syncthreads();
    float* Ts = sm;   // 64*132 floats = 33792 B < 55296 B
    const int tid = threadIdx.x, wid = tid >> 5, lane = tid & 31;
    const int wm = (wid >> 1) * 32, wn = (wid & 1) * 32;
    const int g = lane >> 2, t = lane & 3;
    #pragma unroll
    for (int tm = 0; tm < 2; tm++)
        #pragma unroll
        for (int tn = 0; tn < 4; tn++) {
            int m0 = wm + tm*16 + g, n0 = wn + tn*8 + 2*t;
            Ts[(n0    )*132 + m0    ] = acc[tm][tn][0];
            Ts[(n0 + 1)*132 + m0    ] = acc[tm][tn][1];
            Ts[(n0    )*132 + m0 + 8] = acc[tm][tn][2];
            Ts[(n0 + 1)*132 + m0 + 8] = acc[tm][tn][3];
        }
    __syncthreads();

    const int n = bm >> 10, pbase = bm & 1023;
    float* outb = g_ws2 + (size_t)n*EE_*PP_ + pbase;
    #pragma unroll
    for (int i = 0; i < 8; i++) {
        int id = tid + i*256;
        int hr = id >> 5, seg = id & 31;
        float4 v = *(const float4*)(Ts + hr*132 + seg*4);
        v.x = rnd_tf32(v.x); v.y = rnd_tf32(v.y);
        v.z = rnd_tf32(v.z); v.w = rnd_tf32(v.w);
        *(float4*)(outb + (size_t)(bn + hr)*PP_ + seg*4) = v;
    }
}

// ---------------------------------------------------------------------------
// Stage 2: y[n][p][h*64+r] = rnd( sum_j amat[h][p][j] * ws2[n][h*64+r][j] )
// grid (x: n 0..63 fastest for amat L2 reuse, y: h*8 + ptile)
// ---------------------------------------------------------------------------
__global__ __launch_bounds__(256) void k_stage2()
{
    extern __shared__ float sm[];
    const int n  = blockIdx.x;
    const int h  = blockIdx.y >> 3;
    const int pt = blockIdx.y & 7;
    float acc[2][4][4] = {};
    gemm_loop(g_amat + ((size_t)h*PP_ + pt*128)*PP_, PP_,
              g_ws2  + ((size_t)n*EE_ + h*64)*PP_,  PP_, PP_/32, sm, acc);

    const int tid = threadIdx.x, wid = tid >> 5, lane = tid & 31;
    const int wm = (wid >> 1) * 32, wn = (wid & 1) * 32;
    const int g = lane >> 2, t = lane & 3;
    float* yb = g_yr + ((size_t)n*PP_ + pt*128)*EE_ + h*64;
    #pragma unroll
    for (int tm = 0; tm < 2; tm++)
        #pragma unroll
        for (int tn = 0; tn < 4; tn++) {
            int m0 = wm + tm*16 + g, n0 = wn + tn*8 + 2*t;
            float2 v0 = make_float2(rnd_tf32(acc[tm][tn][0]), rnd_tf32(acc[tm][tn][1]));
            float2 v1 = make_float2(rnd_tf32(acc[tm][tn][2]), rnd_tf32(acc[tm][tn][3]));
            *(float2*)(yb + (size_t)(m0    )*EE_ + n0) = v0;
            *(float2*)(yb + (size_t)(m0 + 8)*EE_ + n0) = v1;
        }
}

// ---------------------------------------------------------------------------
// Stage 3: out[m][e] = log_cosh( sum_k y[m][k] * WT[e][k] + b[e] )
// grid (x: 8 e-tiles of 64, y: 512 m-tiles of 128)
// ---------------------------------------------------------------------------
__global__ __launch_bounds__(256) void k_stage3(const float* __restrict__ bias,
                                                float* __restrict__ out)
{
    extern __shared__ float sm[];
    const int bn = blockIdx.x * 64;
    const int bm = blockIdx.y * 128;
    float acc[2][4][4] = {};
    gemm_loop(g_yr + (size_t)bm*EE_, EE_, g_wt + (size_t)bn*EE_, EE_, EE_/32, sm, acc);

    const int tid = threadIdx.x, wid = tid >> 5, lane = tid & 31;
    const int wm = (wid >> 1) * 32, wn = (wid & 1) * 32;
    const int g = lane >> 2, t = lane & 3;
    #pragma unroll
    for (int tn = 0; tn < 4; tn++) {
        int n0 = wn + tn*8 + 2*t;
        float b0 = bias[bn + n0], b1 = bias[bn + n0 + 1];
        #pragma unroll
        for (int tm = 0; tm < 2; tm++) {
            int m0 = bm + wm + tm*16 + g;
            float2 v0 = make_float2(log_cosh_f(acc[tm][tn][0] + b0),
                                    log_cosh_f(acc[tm][tn][1] + b1));
            float2 v1 = make_float2(log_cosh_f(acc[tm][tn][2] + b0),
                                    log_cosh_f(acc[tm][tn][3] + b1));
            *(float2*)(out + (size_t)(m0    )*EE_ + bn + n0) = v0;
            *(float2*)(out + (size_t)(m0 + 8)*EE_ + bn + n0) = v1;
        }
    }
}

// ---------------------------------------------------------------------------
// Prep kernels
// ---------------------------------------------------------------------------
__global__ void k_round_copy(const float* __restrict__ src, float* __restrict__ dst, int n4)
{
    int i = blockIdx.x * blockDim.x + threadIdx.x;
    if (i < n4) {
        float4 v = ((const float4*)src)[i];
        v.x = rnd_tf32(v.x); v.y = rnd_tf32(v.y);
        v.z = rnd_tf32(v.z); v.w = rnd_tf32(v.w);
        ((float4*)dst)[i] = v;
    }
}

__global__ void k_wt(const float* __restrict__ W)   // g_wt[a][b] = rnd(W[b][a])
{
    __shared__ float t[32][33];
    const int bx = blockIdx.x * 32, by = blockIdx.y * 32;
    const int x = threadIdx.x, y = threadIdx.y;     // 32 x 8
    #pragma unroll
    for (int j = 0; j < 32; j += 8)
        t[y+j][x] = W[(size_t)(by + y + j)*EE_ + bx + x];
    __syncthreads();
    #pragma unroll
    for (int j = 0; j < 32; j += 8)
        g_wt[(size_t)(bx + y + j)*EE_ + by + x] = rnd_tf32(t[x][y+j]);
}

__global__ void k_amat(const float* __restrict__ alpha)  // amat[h][p][j] = rnd(alpha[h][(j-p)&1023])
{
    __shared__ float as_[1024];
    const int p = blockIdx.x, h = blockIdx.y;
    const int tid = threadIdx.x;
    for (int i = tid; i < 1024; i += 256) as_[i] = rnd_tf32(alpha[h*1024 + i]);
    __syncthreads();
    float* dst = g_amat + ((size_t)h*PP_ + p) * PP_;
    for (int i = tid; i < 1024; i += 256) dst[i] = as_[(i - p) & 1023];
}

// ---------------------------------------------------------------------------
extern "C" void kernel_launch(void* const* d_in, const int* in_sizes, int n_in,
                              void* d_out, int out_size)
{
    const float* x     = (const float*)d_in[0];
    const float* alpha = (const float*)d_in[1];
    const float* V     = (const float*)d_in[2];
    const float* W     = (const float*)d_in[3];
    const float* b     = (const float*)d_in[4];
    float* out = (float*)d_out;

    void *xr, *vr;
    cudaGetSymbolAddress(&xr, g_xr);
    cudaGetSymbolAddress(&vr, g_vr);

    cudaFuncSetAttribute(k_stage1, cudaFuncAttributeMaxDynamicSharedMemorySize, SMEM_BYTES);
    cudaFuncSetAttribute(k_stage2, cudaFuncAttributeMaxDynamicSharedMemorySize, SMEM_BYTES);
    cudaFuncSetAttribute(k_stage3, cudaFuncAttributeMaxDynamicSharedMemorySize, SMEM_BYTES);

    // Prep: round inputs to tf32, build W^T and alpha_mat
    {
        int n4 = (int)((size_t)MBIG*EE_/4);
        k_round_copy<<<(n4+255)/256, 256>>>(x, (float*)xr, n4);
        int v4 = EE_*EE_/4;
        k_round_copy<<<(v4+255)/256, 256>>>(V, (float*)vr, v4);
        k_wt<<<dim3(16,16), dim3(32,8)>>>(W);
        k_amat<<<dim3(PP_, HH_), 256>>>(alpha);
    }

    // Stage 1: ws2 = (x @ V^T)^T per n          M=65536 N=512 K=512
    k_stage1<<<dim3(8, 512), 256, SMEM_BYTES>>>();
    // Stage 2: y = alpha_mat @ ws per (n,h)     M=1024 N=64 K=1024, batched
    k_stage2<<<dim3(NN_, 64), 256, SMEM_BYTES>>>();
    // Stage 3: out = log_cosh(y @ W + b)        M=65536 N=512 K=512
    k_stage3<<<dim3(8, 512), 256, SMEM_BYTES>>>(b, out);
}

// round 4
// speedup vs baseline: 3.4403x; 1.0950x over previous
#include <cuda_runtime.h>
#include <cstdint>
#include <math.h>

#define NN_ 64
#define PP_ 1024
#define EE_ 512
#define HH_ 8
#define MBIG (NN_*PP_)   // 65536

#define SA 36   // smem row stride (floats)
// dynamic smem: A 2*128*36 + B 2*128*36 floats = 18432 floats = 73728 B
#define SMEM_BYTES 73728

// ---------------- scratch (__device__ globals; no allocs allowed) ----------
__device__ float g_xr  [(size_t)MBIG*EE_];        // x rounded to tf32        128MB
__device__ float g_vr  [(size_t)EE_*EE_];         // V rounded (hr,d)           1MB
__device__ float g_wt  [(size_t)EE_*EE_];         // W^T rounded                1MB
__device__ float g_amat[(size_t)HH_*PP_*PP_];     // alpha_mat rounded         32MB
__device__ float g_ws2 [(size_t)NN_*EE_*PP_];     // ws transposed [n][hr][p] 128MB
__device__ float g_yr  [(size_t)NN_*PP_*EE_];     // y rounded [n][p][hr]     128MB

// ---------------- helpers --------------------------------------------------
__device__ __forceinline__ uint32_t smem_u32(const void* p){
    uint32_t a;
    asm("{ .reg .u64 t; cvta.to.shared.u64 t, %1; cvt.u32.u64 %0, t; }":"=r"(a):"l"(p));
    return a;
}
__device__ __forceinline__ float rnd_tf32(float x){
    uint32_t u; asm("cvt.rna.tf32.f32 %0, %1;":"=r"(u):"f"(x));
    return __uint_as_float(u);
}
__device__ __forceinline__ float log_cosh_f(float v){
    float ax = fabsf(v);
    return ax + log1pf(expf(-2.0f*ax)) - 0.6931471805599453f;
}
__device__ __forceinline__ void mma_tf32(float c[4],
    uint32_t a0, uint32_t a1, uint32_t a2, uint32_t a3, uint32_t b0, uint32_t b1)
{
    asm volatile("mma.sync.aligned.m16n8k8.row.col.f32.tf32.tf32.f32 "
        "{%0,%1,%2,%3}, {%4,%5,%6,%7}, {%8,%9}, {%0,%1,%2,%3};"
        : "+f"(c[0]), "+f"(c[1]), "+f"(c[2]), "+f"(c[3])
        : "r"(a0), "r"(a1), "r"(a2), "r"(a3), "r"(b0), "r"(b1));
}

// ---------------------------------------------------------------------------
// Mainloop: acc(128x128 block) += A(128xK) * B(128xK)^T
// B rows 0..63 come from B0, rows 64..127 from B1 (both K-major, stride ldb).
// BK=32 double-buffered cp.async. 256 thr, warps 2(M)x4(N), warp tile 64x32.
// ---------------------------------------------------------------------------
__device__ __forceinline__ void gemm_loop(
    const float* __restrict__ A, int lda,
    const float* __restrict__ B0, const float* __restrict__ B1, int ldb,
    int kt, float* __restrict__ sm, float acc[4][4][4])
{
    float* sA = sm;                    // 2 * 128 * SA
    float* sB = sm + 2*128*SA;         // 2 * 128 * SA
    const int tid = threadIdx.x, wid = tid >> 5, lane = tid & 31;
    const int wm = (wid >> 2) * 64, wn = (wid & 3) * 32;
    const int g = lane >> 2, t = lane & 3;

    auto load_tile = [&](int tt, int buf){
        float* dA = sA + buf*128*SA;
        float* dB = sB + buf*128*SA;
        const float* Ab  = A  + tt*32;
        const float* B0b = B0 + tt*32;
        const float* B1b = B1 + tt*32;
        #pragma unroll
        for (int i = 0; i < 4; i++) {                 // A: 128 rows x 8 float4
            int c = tid + i*256, row = c >> 3, seg = c & 7;
            uint32_t dst = smem_u32(dA + row*SA + seg*4);
            asm volatile("cp.async.cg.shared.global [%0], [%1], 16;"
                         :: "r"(dst), "l"(Ab + (size_t)row*lda + seg*4));
        }
        #pragma unroll
        for (int i = 0; i < 4; i++) {                 // B: 128 rows x 8 float4
            int c = tid + i*256, row = c >> 3, seg = c & 7;
            uint32_t dst = smem_u32(dB + row*SA + seg*4);
            const float* src = (i < 2) ? (B0b + (size_t)row*ldb + seg*4)
                                       : (B1b + (size_t)(row-64)*ldb + seg*4);
            asm volatile("cp.async.cg.shared.global [%0], [%1], 16;"
                         :: "r"(dst), "l"(src));
        }
        asm volatile("cp.async.commit_group;" ::: "memory");
    };

    load_tile(0, 0);

    for (int tt = 0; tt < kt; tt++) {
        const int cur = tt & 1;
        if (tt + 1 < kt) {
            load_tile(tt + 1, cur ^ 1);
            asm volatile("cp.async.wait_group 1;" ::: "memory");
        } else {
            asm volatile("cp.async.wait_group 0;" ::: "memory");
        }
        __syncthreads();

        const float* cA = sA + cur*128*SA;
        const float* cB = sB + cur*128*SA;
        #pragma unroll
        for (int ks = 0; ks < 4; ks++) {
            const int k0 = ks * 8;
            uint32_t af[4][4], bf[4][2];
            #pragma unroll
            for (int tm = 0; tm < 4; tm++) {
                const float* ap = cA + (wm + tm*16 + g)*SA + k0 + t;
                af[tm][0] = __float_as_uint(ap[0]);
                af[tm][1] = __float_as_uint(ap[8*SA]);
                af[tm][2] = __float_as_uint(ap[4]);
                af[tm][3] = __float_as_uint(ap[8*SA + 4]);
            }
            #pragma unroll
            for (int tn = 0; tn < 4; tn++) {
                const float* bp = cB + (wn + tn*8 + g)*SA + k0 + t;
                bf[tn][0] = __float_as_uint(bp[0]);
                bf[tn][1] = __float_as_uint(bp[4]);
            }
            #pragma unroll
            for (int tm = 0; tm < 4; tm++)
                #pragma unroll
                for (int tn = 0; tn < 4; tn++)
                    mma_tf32(acc[tm][tn], af[tm][0], af[tm][1], af[tm][2], af[tm][3],
                             bf[tn][0], bf[tn][1]);
        }
        __syncthreads();
    }
}

// ---------------------------------------------------------------------------
// Stage 1: ws2[n][hr][p] = rnd( sum_d x[n,p,d] * V[hr,d] )  (transposed store)
// grid (x: 4 hr-tiles of 128, y: 512 m-tiles of 128)
// ---------------------------------------------------------------------------
__global__ __launch_bounds__(256, 2) void k_stage1()
{
    extern __shared__ float sm[];
    const int bn = blockIdx.x * 128;
    const int bm = blockIdx.y * 128;
    const float* Bb = g_vr + (size_t)bn*EE_;
    float acc[4][4][4] = {};
    gemm_loop(g_xr + (size_t)bm*EE_, EE_, Bb, Bb + (size_t)64*EE_, EE_, EE_/32, sm, acc);

    // transpose C (128m x 128n) through smem: Ts[n][m], stride 132
    __syncthreads();
    float* Ts = sm;   // 128*132 floats = 67584 B <= 73728 B
    const int tid = threadIdx.x, wid = tid >> 5, lane = tid & 31;
    const int wm = (wid >> 2) * 64, wn = (wid & 3) * 32;
    const int g = lane >> 2, t = lane & 3;
    #pragma unroll
    for (int tm = 0; tm < 4; tm++)
        #pragma unroll
        for (int tn = 0; tn < 4; tn++) {
            int m0 = wm + tm*16 + g, n0 = wn + tn*8 + 2*t;
            Ts[(n0    )*132 + m0    ] = acc[tm][tn][0];
            Ts[(n0 + 1)*132 + m0    ] = acc[tm][tn][1];
            Ts[(n0    )*132 + m0 + 8] = acc[tm][tn][2];
            Ts[(n0 + 1)*132 + m0 + 8] = acc[tm][tn][3];
        }
    __syncthreads();

    const int n = bm >> 10, pbase = bm & 1023;
    float* outb = g_ws2 + (size_t)n*EE_*PP_ + pbase;
    #pragma unroll
    for (int i = 0; i < 16; i++) {
        int id = tid + i*256;
        int hr = id >> 5, seg = id & 31;
        float4 v = *(const float4*)(Ts + hr*132 + seg*4);
        v.x = rnd_tf32(v.x); v.y = rnd_tf32(v.y);
        v.z = rnd_tf32(v.z); v.w = rnd_tf32(v.w);
        *(float4*)(outb + (size_t)(bn + hr)*PP_ + seg*4) = v;
    }
}

// ---------------------------------------------------------------------------
// Stage 2: y[n][p][h*64+r] = rnd( sum_j amat[h][p][j] * ws2[n][h*64+r][j] )
// Two n per block: B rows 0..63 = ws2(n0,h), 64..127 = ws2(n0+1,h).
// grid (x: 32 n-pairs fastest for amat L2 reuse, y: h*8 + ptile)
// ---------------------------------------------------------------------------
__global__ __launch_bounds__(256, 2) void k_stage2()
{
    extern __shared__ float sm[];
    const int n0 = blockIdx.x * 2;
    const int h  = blockIdx.y >> 3;
    const int pt = blockIdx.y & 7;
    float acc[4][4][4] = {};
    gemm_loop(g_amat + ((size_t)h*PP_ + pt*128)*PP_, PP_,
              g_ws2  + ((size_t)n0*EE_ + h*64)*PP_,
              g_ws2  + ((size_t)(n0+1)*EE_ + h*64)*PP_, PP_, PP_/32, sm, acc);

    const int tid = threadIdx.x, wid = tid >> 5, lane = tid & 31;
    const int wm = (wid >> 2) * 64, wn = (wid & 3) * 32;
    const int g = lane >> 2, t = lane & 3;
    const int nsel = wn >> 6;            // warp's n-half: 0 -> n0, 1 -> n0+1
    float* yb = g_yr + ((size_t)(n0 + nsel)*PP_ + pt*128)*EE_ + h*64;
    #pragma unroll
    for (int tm = 0; tm < 4; tm++)
        #pragma unroll
        for (int tn = 0; tn < 4; tn++) {
            int m0 = wm + tm*16 + g;
            int r  = (wn & 63) + tn*8 + 2*t;
            float2 v0 = make_float2(rnd_tf32(acc[tm][tn][0]), rnd_tf32(acc[tm][tn][1]));
            float2 v1 = make_float2(rnd_tf32(acc[tm][tn][2]), rnd_tf32(acc[tm][tn][3]));
            *(float2*)(yb + (size_t)(m0    )*EE_ + r) = v0;
            *(float2*)(yb + (size_t)(m0 + 8)*EE_ + r) = v1;
        }
}

// ---------------------------------------------------------------------------
// Stage 3: out[m][e] = log_cosh( sum_k y[m][k] * WT[e][k] + b[e] )
// grid (x: 4 e-tiles of 128, y: 512 m-tiles of 128)
// ---------------------------------------------------------------------------
__global__ __launch_bounds__(256, 2) void k_stage3(const float* __restrict__ bias,
                                                   float* __restrict__ out)
{
    extern __shared__ float sm[];
    const int bn = blockIdx.x * 128;
    const int bm = blockIdx.y * 128;
    const float* Bb = g_wt + (size_t)bn*EE_;
    float acc[4][4][4] = {};
    gemm_loop(g_yr + (size_t)bm*EE_, EE_, Bb, Bb + (size_t)64*EE_, EE_, EE_/32, sm, acc);

    const int tid = threadIdx.x, wid = tid >> 5, lane = tid & 31;
    const int wm = (wid >> 2) * 64, wn = (wid & 3) * 32;
    const int g = lane >> 2, t = lane & 3;
    #pragma unroll
    for (int tn = 0; tn < 4; tn++) {
        int n0 = wn + tn*8 + 2*t;
        float b0 = bias[bn + n0], b1 = bias[bn + n0 + 1];
        #pragma unroll
        for (int tm = 0; tm < 4; tm++) {
            int m0 = bm + wm + tm*16 + g;
            float2 v0 = make_float2(log_cosh_f(acc[tm][tn][0] + b0),
                                    log_cosh_f(acc[tm][tn][1] + b1));
            float2 v1 = make_float2(log_cosh_f(acc[tm][tn][2] + b0),
                                    log_cosh_f(acc[tm][tn][3] + b1));
            *(float2*)(out + (size_t)(m0    )*EE_ + bn + n0) = v0;
            *(float2*)(out + (size_t)(m0 + 8)*EE_ + bn + n0) = v1;
        }
    }
}

// ---------------------------------------------------------------------------
// Prep kernels
// ---------------------------------------------------------------------------
__global__ void k_round_copy(const float* __restrict__ src, float* __restrict__ dst, int n4)
{
    int i = blockIdx.x * blockDim.x + threadIdx.x;
    if (i < n4) {
        float4 v = ((const float4*)src)[i];
        v.x = rnd_tf32(v.x); v.y = rnd_tf32(v.y);
        v.z = rnd_tf32(v.z); v.w = rnd_tf32(v.w);
        ((float4*)dst)[i] = v;
    }
}

__global__ void k_wt(const float* __restrict__ W)   // g_wt[a][b] = rnd(W[b][a])
{
    __shared__ float t[32][33];
    const int bx = blockIdx.x * 32, by = blockIdx.y * 32;
    const int x = threadIdx.x, y = threadIdx.y;     // 32 x 8
    #pragma unroll
    for (int j = 0; j < 32; j += 8)
        t[y+j][x] = W[(size_t)(by + y + j)*EE_ + bx + x];
    __syncthreads();
    #pragma unroll
    for (int j = 0; j < 32; j += 8)
        g_wt[(size_t)(bx + y + j)*EE_ + by + x] = rnd_tf32(t[x][y+j]);
}

__global__ void k_amat(const float* __restrict__ alpha)  // amat[h][p][j] = rnd(alpha[h][(j-p)&1023])
{
    __shared__ float as_[1024];
    const int p = blockIdx.x, h = blockIdx.y;
    const int tid = threadIdx.x;
    for (int i = tid; i < 1024; i += 256) as_[i] = rnd_tf32(alpha[h*1024 + i]);
    __syncthreads();
    float* dst = g_amat + ((size_t)h*PP_ + p) * PP_;
    for (int i = tid; i < 1024; i += 256) dst[i] = as_[(i - p) & 1023];
}

// ---------------------------------------------------------------------------
extern "C" void kernel_launch(void* const* d_in, const int* in_sizes, int n_in,
                              void* d_out, int out_size)
{
    const float* x     = (const float*)d_in[0];
    const float* alpha = (const float*)d_in[1];
    const float* V     = (const float*)d_in[2];
    const float* W     = (const float*)d_in[3];
    const float* b     = (const float*)d_in[4];
    float* out = (float*)d_out;

    void *xr, *vr;
    cudaGetSymbolAddress(&xr, g_xr);
    cudaGetSymbolAddress(&vr, g_vr);

    cudaFuncSetAttribute(k_stage1, cudaFuncAttributeMaxDynamicSharedMemorySize, SMEM_BYTES);
    cudaFuncSetAttribute(k_stage2, cudaFuncAttributeMaxDynamicSharedMemorySize, SMEM_BYTES);
    cudaFuncSetAttribute(k_stage3, cudaFuncAttributeMaxDynamicSharedMemorySize, SMEM_BYTES);

    // Prep: round inputs to tf32, build W^T and alpha_mat
    {
        int n4 = (int)((size_t)MBIG*EE_/4);
        k_round_copy<<<(n4+255)/256, 256>>>(x, (float*)xr, n4);
        int v4 = EE_*EE_/4;
        k_round_copy<<<(v4+255)/256, 256>>>(V, (float*)vr, v4);
        k_wt<<<dim3(16,16), dim3(32,8)>>>(W);
        k_amat<<<dim3(PP_, HH_), 256>>>(alpha);
    }

    // Stage 1: ws2 = (x @ V^T)^T per n          M=65536 N=512 K=512
    k_stage1<<<dim3(4, 512), 256, SMEM_BYTES>>>();
    // Stage 2: y = alpha_mat @ ws, two n/block  M=1024 N=128 K=1024
    k_stage2<<<dim3(32, 64), 256, SMEM_BYTES>>>();
    // Stage 3: out = log_cosh(y @ W + b)        M=65536 N=512 K=512
    k_stage3<<<dim3(4, 512), 256, SMEM_BYTES>>>(b, out);
}

// round 5
// speedup vs baseline: 3.6562x; 1.0628x over previous
#include <cuda_runtime.h>
#include <cstdint>
#include <math.h>

#define NN_ 64
#define PP_ 1024
#define EE_ 512
#define HH_ 8
#define MBIG (NN_*PP_)   // 65536

#define SA 36   // smem row stride (floats)
// dynamic smem: 3 stages x (A 128*36 + B 128*36) floats = 110592 B
#define SMEM_BYTES 110592

// ---------------- scratch (__device__ globals; no allocs allowed) ----------
__device__ float g_vr  [(size_t)EE_*EE_];         // V rounded (hr,d)           1MB
__device__ float g_wt  [(size_t)EE_*EE_];         // W^T rounded                1MB
__device__ float g_amat[(size_t)HH_*PP_*PP_];     // alpha_mat rounded         32MB
__device__ float g_ws2 [(size_t)NN_*EE_*PP_];     // ws transposed [n][hr][p] 128MB
__device__ float g_yr  [(size_t)NN_*PP_*EE_];     // y rounded [n][p][hr]     128MB

// ---------------- helpers --------------------------------------------------
__device__ __forceinline__ uint32_t smem_u32(const void* p){
    uint32_t a;
    asm("{ .reg .u64 t; cvta.to.shared.u64 t, %1; cvt.u32.u64 %0, t; }":"=r"(a):"l"(p));
    return a;
}
__device__ __forceinline__ float rnd_tf32(float x){
    uint32_t u; asm("cvt.rna.tf32.f32 %0, %1;":"=r"(u):"f"(x));
    return __uint_as_float(u);
}
__device__ __forceinline__ uint32_t rnd_tf32_u(float x){
    uint32_t u; asm("cvt.rna.tf32.f32 %0, %1;":"=r"(u):"f"(x));
    return u;
}
__device__ __forceinline__ float log_cosh_f(float v){
    float ax = fabsf(v);
    return ax + log1pf(expf(-2.0f*ax)) - 0.6931471805599453f;
}
__device__ __forceinline__ void mma_tf32(float c[4],
    uint32_t a0, uint32_t a1, uint32_t a2, uint32_t a3, uint32_t b0, uint32_t b1)
{
    asm volatile("mma.sync.aligned.m16n8k8.row.col.f32.tf32.tf32.f32 "
        "{%0,%1,%2,%3}, {%4,%5,%6,%7}, {%8,%9}, {%0,%1,%2,%3};"
        : "+f"(c[0]), "+f"(c[1]), "+f"(c[2]), "+f"(c[3])
        : "r"(a0), "r"(a1), "r"(a2), "r"(a3), "r"(b0), "r"(b1));
}

// ---------------------------------------------------------------------------
// Mainloop: acc(128x128 block) += A(128xK) * B(128xK)^T
// B rows 0..63 from B0, 64..127 from B1 (both K-major, stride ldb).
// BK=32, 3-stage cp.async pipeline, ONE __syncthreads per k-tile.
// 256 thr, warps 2(M)x4(N), warp tile 64x32.
// RND_A: round A fragments to tf32 in-register (for raw-fp32 A input).
// ---------------------------------------------------------------------------
template<bool RND_A>
__device__ __forceinline__ void gemm_loop(
    const float* __restrict__ A, int lda,
    const float* __restrict__ B0, const float* __restrict__ B1, int ldb,
    int kt, float* __restrict__ sm, float acc[4][4][4])
{
    const int tid = threadIdx.x, wid = tid >> 5, lane = tid & 31;
    const int wm = (wid >> 2) * 64, wn = (wid & 3) * 32;
    const int g = lane >> 2, t = lane & 3;

    auto load_tile = [&](int tt, int buf){
        float* dA = sm + buf*(2*128*SA);
        float* dB = dA + 128*SA;
        const float* Ab  = A  + tt*32;
        const float* B0b = B0 + tt*32;
        const float* B1b = B1 + tt*32;
        #pragma unroll
        for (int i = 0; i < 4; i++) {                 // A: 128 rows x 8 float4
            int c = tid + i*256, row = c >> 3, seg = c & 7;
            uint32_t dst = smem_u32(dA + row*SA + seg*4);
            asm volatile("cp.async.cg.shared.global [%0], [%1], 16;"
                         :: "r"(dst), "l"(Ab + (size_t)row*lda + seg*4));
        }
        #pragma unroll
        for (int i = 0; i < 4; i++) {                 // B: 128 rows x 8 float4
            int c = tid + i*256, row = c >> 3, seg = c & 7;
            uint32_t dst = smem_u32(dB + row*SA + seg*4);
            const float* src = (i < 2) ? (B0b + (size_t)row*ldb + seg*4)
                                       : (B1b + (size_t)(row-64)*ldb + seg*4);
            asm volatile("cp.async.cg.shared.global [%0], [%1], 16;"
                         :: "r"(dst), "l"(src));
        }
        asm volatile("cp.async.commit_group;" ::: "memory");
    };

    load_tile(0, 0);
    if (kt > 1) load_tile(1, 1);

    for (int tt = 0; tt < kt; tt++) {
        const int cur = tt % 3;
        asm volatile("cp.async.wait_group 1;" ::: "memory");
        __syncthreads();

        const float* cA = sm + cur*(2*128*SA);
        const float* cB = cA + 128*SA;
        #pragma unroll
        for (int ks = 0; ks < 4; ks++) {
            const int k0 = ks * 8;
            uint32_t af[4][4], bf[4][2];
            #pragma unroll
            for (int tm = 0; tm < 4; tm++) {
                const float* ap = cA + (wm + tm*16 + g)*SA + k0 + t;
                if (RND_A) {
                    af[tm][0] = rnd_tf32_u(ap[0]);
                    af[tm][1] = rnd_tf32_u(ap[8*SA]);
                    af[tm][2] = rnd_tf32_u(ap[4]);
                    af[tm][3] = rnd_tf32_u(ap[8*SA + 4]);
                } else {
                    af[tm][0] = __float_as_uint(ap[0]);
                    af[tm][1] = __float_as_uint(ap[8*SA]);
                    af[tm][2] = __float_as_uint(ap[4]);
                    af[tm][3] = __float_as_uint(ap[8*SA + 4]);
                }
            }
            #pragma unroll
            for (int tn = 0; tn < 4; tn++) {
                const float* bp = cB + (wn + tn*8 + g)*SA + k0 + t;
                bf[tn][0] = __float_as_uint(bp[0]);
                bf[tn][1] = __float_as_uint(bp[4]);
            }
            #pragma unroll
            for (int tm = 0; tm < 4; tm++)
                #pragma unroll
                for (int tn = 0; tn < 4; tn++)
                    mma_tf32(acc[tm][tn], af[tm][0], af[tm][1], af[tm][2], af[tm][3],
                             bf[tn][0], bf[tn][1]);
        }
        if (tt + 2 < kt) load_tile(tt + 2, (tt + 2) % 3);
    }
}

// ---------------------------------------------------------------------------
// Stage 1: ws2[n][hr][p] = rnd( sum_d x[n,p,d] * V[hr,d] )  (transposed store)
// A = raw fp32 x (rounded in-register). grid (x: 4 hr-tiles, y: 512 m-tiles)
// ---------------------------------------------------------------------------
__global__ __launch_bounds__(256) void k_stage1(const float* __restrict__ x)
{
    extern __shared__ float sm[];
    const int bn = blockIdx.x * 128;
    const int bm = blockIdx.y * 128;
    const float* Bb = g_vr + (size_t)bn*EE_;
    float acc[4][4][4] = {};
    gemm_loop<true>(x + (size_t)bm*EE_, EE_, Bb, Bb + (size_t)64*EE_, EE_, EE_/32, sm, acc);

    // transpose C (128m x 128n) through smem: Ts[n][m], stride 132
    __syncthreads();
    float* Ts = sm;   // 128*132*4 = 67584 B <= SMEM_BYTES
    const int tid = threadIdx.x, wid = tid >> 5, lane = tid & 31;
    const int wm = (wid >> 2) * 64, wn = (wid & 3) * 32;
    const int g = lane >> 2, t = lane & 3;
    #pragma unroll
    for (int tm = 0; tm < 4; tm++)
        #pragma unroll
        for (int tn = 0; tn < 4; tn++) {
            int m0 = wm + tm*16 + g, n0 = wn + tn*8 + 2*t;
            Ts[(n0    )*132 + m0    ] = acc[tm][tn][0];
            Ts[(n0 + 1)*132 + m0    ] = acc[tm][tn][1];
            Ts[(n0    )*132 + m0 + 8] = acc[tm][tn][2];
            Ts[(n0 + 1)*132 + m0 + 8] = acc[tm][tn][3];
        }
    __syncthreads();

    const int n = bm >> 10, pbase = bm & 1023;
    float* outb = g_ws2 + (size_t)n*EE_*PP_ + pbase;
    #pragma unroll
    for (int i = 0; i < 16; i++) {
        int id = tid + i*256;
        int hr = id >> 5, seg = id & 31;
        float4 v = *(const float4*)(Ts + hr*132 + seg*4);
        v.x = rnd_tf32(v.x); v.y = rnd_tf32(v.y);
        v.z = rnd_tf32(v.z); v.w = rnd_tf32(v.w);
        *(float4*)(outb + (size_t)(bn + hr)*PP_ + seg*4) = v;
    }
}

// ---------------------------------------------------------------------------
// Stage 2: y[n][p][h*64+r] = rnd( sum_j amat[h][p][j] * ws2[n][h*64+r][j] )
// Two n per block. grid (x: 32 n-pairs fastest, y: h*8 + ptile)
// ---------------------------------------------------------------------------
__global__ __launch_bounds__(256) void k_stage2()
{
    extern __shared__ float sm[];
    const int n0 = blockIdx.x * 2;
    const int h  = blockIdx.y >> 3;
    const int pt = blockIdx.y & 7;
    float acc[4][4][4] = {};
    gemm_loop<false>(g_amat + ((size_t)h*PP_ + pt*128)*PP_, PP_,
                     g_ws2  + ((size_t)n0*EE_ + h*64)*PP_,
                     g_ws2  + ((size_t)(n0+1)*EE_ + h*64)*PP_, PP_, PP_/32, sm, acc);

    const int tid = threadIdx.x, wid = tid >> 5, lane = tid & 31;
    const int wm = (wid >> 2) * 64, wn = (wid & 3) * 32;
    const int g = lane >> 2, t = lane & 3;
    const int nsel = wn >> 6;            // warp's n-half: 0 -> n0, 1 -> n0+1
    float* yb = g_yr + ((size_t)(n0 + nsel)*PP_ + pt*128)*EE_ + h*64;
    #pragma unroll
    for (int tm = 0; tm < 4; tm++)
        #pragma unroll
        for (int tn = 0; tn < 4; tn++) {
            int m0 = wm + tm*16 + g;
            int r  = (wn & 63) + tn*8 + 2*t;
            float2 v0 = make_float2(rnd_tf32(acc[tm][tn][0]), rnd_tf32(acc[tm][tn][1]));
            float2 v1 = make_float2(rnd_tf32(acc[tm][tn][2]), rnd_tf32(acc[tm][tn][3]));
            *(float2*)(yb + (size_t)(m0    )*EE_ + r) = v0;
            *(float2*)(yb + (size_t)(m0 + 8)*EE_ + r) = v1;
        }
}

// ---------------------------------------------------------------------------
// Stage 3: out[m][e] = log_cosh( sum_k y[m][k] * WT[e][k] + b[e] )
// grid (x: 4 e-tiles of 128, y: 512 m-tiles of 128)
// ---------------------------------------------------------------------------
__global__ __launch_bounds__(256) void k_stage3(const float* __restrict__ bias,
                                                float* __restrict__ out)
{
    extern __shared__ float sm[];
    const int bn = blockIdx.x * 128;
    const int bm = blockIdx.y * 128;
    const float* Bb = g_wt + (size_t)bn*EE_;
    float acc[4][4][4] = {};
    gemm_loop<false>(g_yr + (size_t)bm*EE_, EE_, Bb, Bb + (size_t)64*EE_, EE_, EE_/32, sm, acc);

    const int tid = threadIdx.x, wid = tid >> 5, lane = tid & 31;
    const int wm = (wid >> 2) * 64, wn = (wid & 3) * 32;
    const int g = lane >> 2, t = lane & 3;
    #pragma unroll
    for (int tn = 0; tn < 4; tn++) {
        int n0 = wn + tn*8 + 2*t;
        float b0 = bias[bn + n0], b1 = bias[bn + n0 + 1];
        #pragma unroll
        for (int tm = 0; tm < 4; tm++) {
            int m0 = bm + wm + tm*16 + g;
            float2 v0 = make_float2(log_cosh_f(acc[tm][tn][0] + b0),
                                    log_cosh_f(acc[tm][tn][1] + b1));
            float2 v1 = make_float2(log_cosh_f(acc[tm][tn][2] + b0),
                                    log_cosh_f(acc[tm][tn][3] + b1));
            *(float2*)(out + (size_t)(m0    )*EE_ + bn + n0) = v0;
            *(float2*)(out + (size_t)(m0 + 8)*EE_ + bn + n0) = v1;
        }
    }
}

// ---------------------------------------------------------------------------
// Prep kernels
// ---------------------------------------------------------------------------
__global__ void k_round_copy(const float* __restrict__ src, float* __restrict__ dst, int n4)
{
    int i = blockIdx.x * blockDim.x + threadIdx.x;
    if (i < n4) {
        float4 v = ((const float4*)src)[i];
        v.x = rnd_tf32(v.x); v.y = rnd_tf32(v.y);
        v.z = rnd_tf32(v.z); v.w = rnd_tf32(v.w);
        ((float4*)dst)[i] = v;
    }
}

__global__ void k_wt(const float* __restrict__ W)   // g_wt[a][b] = rnd(W[b][a])
{
    __shared__ float t[32][33];
    const int bx = blockIdx.x * 32, by = blockIdx.y * 32;
    const int x = threadIdx.x, y = threadIdx.y;     // 32 x 8
    #pragma unroll
    for (int j = 0; j < 32; j += 8)
        t[y+j][x] = W[(size_t)(by + y + j)*EE_ + bx + x];
    __syncthreads();
    #pragma unroll
    for (int j = 0; j < 32; j += 8)
        g_wt[(size_t)(bx + y + j)*EE_ + by + x] = rnd_tf32(t[x][y+j]);
}

__global__ void k_amat(const float* __restrict__ alpha)  // amat[h][p][j] = rnd(alpha[h][(j-p)&1023])
{
    __shared__ float as_[1024];
    const int p = blockIdx.x, h = blockIdx.y;
    const int tid = threadIdx.x;
    for (int i = tid; i < 1024; i += 256) as_[i] = rnd_tf32(alpha[h*1024 + i]);
    __syncthreads();
    float* dst = g_amat + ((size_t)h*PP_ + p) * PP_;
    for (int i = tid; i < 1024; i += 256) dst[i] = as_[(i - p) & 1023];
}

// ---------------------------------------------------------------------------
extern "C" void kernel_launch(void* const* d_in, const int* in_sizes, int n_in,
                              void* d_out, int out_size)
{
    const float* x     = (const float*)d_in[0];
    const float* alpha = (const float*)d_in[1];
    const float* V     = (const float*)d_in[2];
    const float* W     = (const float*)d_in[3];
    const float* b     = (const float*)d_in[4];
    float* out = (float*)d_out;

    void *vr;
    cudaGetSymbolAddress(&vr, g_vr);

    cudaFuncSetAttribute(k_stage1, cudaFuncAttributeMaxDynamicSharedMemorySize, SMEM_BYTES);
    cudaFuncSetAttribute(k_stage2, cudaFuncAttributeMaxDynamicSharedMemorySize, SMEM_BYTES);
    cudaFuncSetAttribute(k_stage3, cudaFuncAttributeMaxDynamicSharedMemorySize, SMEM_BYTES);

    // Prep: round V, build W^T and alpha_mat (x is rounded in-register in stage 1)
    {
        int v4 = EE_*EE_/4;
        k_round_copy<<<(v4+255)/256, 256>>>(V, (float*)vr, v4);
        k_wt<<<dim3(16,16), dim3(32,8)>>>(W);
        k_amat<<<dim3(PP_, HH_), 256>>>(alpha);
    }

    // Stage 1: ws2 = (x @ V^T)^T per n          M=65536 N=512 K=512
    k_stage1<<<dim3(4, 512), 256, SMEM_BYTES>>>(x);
    // Stage 2: y = alpha_mat @ ws, two n/block  M=1024 N=128 K=1024
    k_stage2<<<dim3(32, 64), 256, SMEM_BYTES>>>();
    // Stage 3: out = log_cosh(y @ W + b)        M=65536 N=512 K=512
    k_stage3<<<dim3(4, 512), 256, SMEM_BYTES>>>(b, out);
}

// round 6
// speedup vs baseline: 4.2258x; 1.1558x over previous
#include <cuda_runtime.h>
#include <cstdint>
#include <math.h>

#define NN_ 64
#define PP_ 1024
#define EE_ 512
#define HH_ 8
#define MBIG (NN_*PP_)   // 65536

// dynamic smem: 3 stages x (A 4096 + B 4096 floats) = 24576 floats = 98304 B
#define SMEM_BYTES 98304

// ---------------- scratch (__device__ globals; no allocs allowed) ----------
// Packed-A panels: per 128 rows: [K/8][8 rt][32 l][4f]; group(l)= {A[g][t],A[g+8][t],A[g][t+4],A[g+8][t+4]}
// Packed-B panels: [K/8][nb][32 l][2f]; group(l) = {B[nb*8+g][t], B[nb*8+g][t+4]}
__device__ float g_xa [(size_t)512*65536];   // x packed-A, 512 panels       128MB
__device__ float g_vp [(size_t)EE_*EE_];     // V packed-B  [64 k8][64 nb]     1MB
__device__ float g_wp [(size_t)EE_*EE_];     // W^T packed-B                   1MB
__device__ float g_ap [(size_t)64*131072];   // alpha_mat packed-A, 64 panels 32MB
__device__ float g_wsp[(size_t)512*65536];   // ws packed-B per (n,h): [128 k8][8 nb] 128MB
__device__ float g_yp [(size_t)512*65536];   // y packed-A, 512 panels       128MB

// ---------------- helpers --------------------------------------------------
__device__ __forceinline__ uint32_t smem_u32(const void* p){
    uint32_t a;
    asm("{ .reg .u64 t; cvta.to.shared.u64 t, %1; cvt.u32.u64 %0, t; }":"=r"(a):"l"(p));
    return a;
}
__device__ __forceinline__ float rnd_tf32(float x){
    uint32_t u; asm("cvt.rna.tf32.f32 %0, %1;":"=r"(u):"f"(x));
    return __uint_as_float(u);
}
__device__ __forceinline__ float log_cosh_f(float v){
    float ax = fabsf(v);
    return ax + log1pf(expf(-2.0f*ax)) - 0.6931471805599453f;
}
__device__ __forceinline__ void mma_tf32(float c[4],
    uint32_t a0, uint32_t a1, uint32_t a2, uint32_t a3, uint32_t b0, uint32_t b1)
{
    asm volatile("mma.sync.aligned.m16n8k8.row.col.f32.tf32.tf32.f32 "
        "{%0,%1,%2,%3}, {%4,%5,%6,%7}, {%8,%9}, {%0,%1,%2,%3};"
        : "+f"(c[0]), "+f"(c[1]), "+f"(c[2]), "+f"(c[3])
        : "r"(a0), "r"(a1), "r"(a2), "r"(a3), "r"(b0), "r"(b1));
}

// ---------------------------------------------------------------------------
// Mainloop: acc(128x128) += A(128xK) * B(128xK)^T, operands pre-packed in
// fragment-major order. BK=32 (4 k8 per tile), 3-stage cp.async pipeline,
// one __syncthreads per tile. 256 thr, warps 2(M)x4(N), warp tile 64x32.
// A slab per tile: 16KB contiguous at Ap + tt*4096 floats.
// B slab per k8: chunks 0..127 from B0, 128..255 from B1; per-k8 stride bstride.
// ---------------------------------------------------------------------------
__device__ __forceinline__ void gemm_loop(
    const float* __restrict__ Ap,
    const float* __restrict__ B0, const float* __restrict__ B1,
    size_t bstride, int kt, float* __restrict__ sm, float acc[4][4][4])
{
    const int tid = threadIdx.x, wid = tid >> 5, lane = tid & 31;
    const int wrt = (wid >> 2) * 4;   // A rt base (row/16): 0 or 4
    const int wnb = (wid & 3) * 4;    // B nb base (row/8): 0,4,8,12

    auto load_tile = [&](int tt, int buf){
        float* dA = sm + buf*8192;
        float* dB = dA + 4096;
        const float* As = Ap + (size_t)tt*4096;
        #pragma unroll
        for (int i = 0; i < 4; i++) {
            int c = tid + i*256;
            uint32_t dst = smem_u32(dA + c*4);
            asm volatile("cp.async.cg.shared.global [%0], [%1], 16;"
                         :: "r"(dst), "l"(As + c*4));
        }
        #pragma unroll
        for (int i = 0; i < 4; i++) {
            int c = tid + i*256;
            int k8 = c >> 8, r = c & 255;
            const float* src = ((r & 128) ? B1 : B0)
                             + (size_t)(tt*4 + k8)*bstride + (r & 127)*4;
            uint32_t dst = smem_u32(dB + c*4);
            asm volatile("cp.async.cg.shared.global [%0], [%1], 16;"
                         :: "r"(dst), "l"(src));
        }
        asm volatile("cp.async.commit_group;" ::: "memory");
    };

    load_tile(0, 0);
    if (kt > 1) load_tile(1, 1);

    for (int tt = 0; tt < kt; tt++) {
        const int cur = tt % 3;
        asm volatile("cp.async.wait_group 1;" ::: "memory");
        __syncthreads();
        if (tt + 2 < kt) load_tile(tt + 2, (tt + 2) % 3);

        const float4* fA = (const float4*)(sm + cur*8192);
        const float2* fB = (const float2*)(sm + cur*8192 + 4096);
        #pragma unroll
        for (int ks = 0; ks < 4; ks++) {
            float4 a[4]; float2 b[4];
            #pragma unroll
            for (int tm = 0; tm < 4; tm++)
                a[tm] = fA[ks*256 + (wrt + tm)*32 + lane];
            #pragma unroll
            for (int tn = 0; tn < 4; tn++)
                b[tn] = fB[ks*512 + (wnb + tn)*32 + lane];
            #pragma unroll
            for (int tm = 0; tm < 4; tm++)
                #pragma unroll
                for (int tn = 0; tn < 4; tn++)
                    mma_tf32(acc[tm][tn],
                             __float_as_uint(a[tm].x), __float_as_uint(a[tm].y),
                             __float_as_uint(a[tm].z), __float_as_uint(a[tm].w),
                             __float_as_uint(b[tn].x), __float_as_uint(b[tn].y));
        }
    }
}

// ---------------------------------------------------------------------------
// Stage 1: ws[n,p,hr] = x @ V^T; epilogue writes packed-B slabs g_wsp[(n,h)]
// grid (x: 4 hr-tiles of 128, y: 512 m-tiles of 128)
// ---------------------------------------------------------------------------
__global__ __launch_bounds__(256, 2) void k_stage1()
{
    extern __shared__ float sm[];
    const int bn = blockIdx.x * 128;    // hr tile
    const int bm = blockIdx.y * 128;    // m tile
    float acc[4][4][4] = {};
    const float* b0 = g_vp + (bn >> 3) * 64;
    gemm_loop(g_xa + (size_t)(bm >> 7)*65536, b0, b0 + 512, 4096, 16, sm, acc);

    __syncthreads();
    float* Ts = sm;   // Ts[hrloc][ploc], stride 132 (transposed C)
    const int tid = threadIdx.x, wid = tid >> 5, lane = tid & 31;
    const int wm = (wid >> 2) * 64, wn = (wid & 3) * 32;
    const int gg = lane >> 2, tt_ = lane & 3;
    #pragma unroll
    for (int tm = 0; tm < 4; tm++)
        #pragma unroll
        for (int tn = 0; tn < 4; tn++) {
            int m0 = wm + tm*16 + gg, n0 = wn + tn*8 + 2*tt_;
            Ts[(n0    )*132 + m0    ] = acc[tm][tn][0];
            Ts[(n0 + 1)*132 + m0    ] = acc[tm][tn][1];
            Ts[(n0    )*132 + m0 + 8] = acc[tm][tn][2];
            Ts[(n0 + 1)*132 + m0 + 8] = acc[tm][tn][3];
        }
    __syncthreads();

    const int n = bm >> 10, pbase = bm & 1023;
    #pragma unroll
    for (int i = 0; i < 16; i++) {
        int u = tid + i*256;
        int k8rel = u >> 8, nbrel = (u >> 4) & 15, lp = u & 15;
        int g2 = lp >> 1, tp = (lp & 1) * 2;
        int hrloc = nbrel*8 + g2;
        int hrAbs = bn + hrloc;
        const float* ts = Ts + hrloc*132 + k8rel*8 + tp;
        float4 v;
        v.x = rnd_tf32(ts[0]); v.y = rnd_tf32(ts[4]);
        v.z = rnd_tf32(ts[1]); v.w = rnd_tf32(ts[5]);
        size_t dst = (size_t)(n*8 + (hrAbs >> 6))*65536
                   + (size_t)((pbase >> 3) + k8rel)*512
                   + ((hrAbs >> 3) & 7)*64 + (g2*4 + tp)*2;
        *(float4*)(g_wsp + dst) = v;
    }
}

// ---------------------------------------------------------------------------
// Stage 2: y[n,p,h*64+r] = alpha_mat @ ws; epilogue writes packed-A g_yp.
// Two n per block (B halves). grid (x: 32 n-pairs, y: h*8 + ptile)
// ---------------------------------------------------------------------------
__global__ __launch_bounds__(256, 2) void k_stage2()
{
    extern __shared__ float sm[];
    const int n0 = blockIdx.x * 2;
    const int h  = blockIdx.y >> 3;
    const int pt = blockIdx.y & 7;
    float acc[4][4][4] = {};
    gemm_loop(g_ap + (size_t)(h*8 + pt)*131072,
              g_wsp + (size_t)(n0*8 + h)*65536,
              g_wsp + (size_t)((n0+1)*8 + h)*65536,
              512, 32, sm, acc);

    __syncthreads();
    float* S = sm;   // S[ploc][col], stride 132
    const int tid = threadIdx.x, wid = tid >> 5, lane = tid & 31;
    const int wm = (wid >> 2) * 64, wn = (wid & 3) * 32;
    const int gg = lane >> 2, tt_ = lane & 3;
    #pragma unroll
    for (int tm = 0; tm < 4; tm++)
        #pragma unroll
        for (int tn = 0; tn < 4; tn++) {
            int m0 = wm + tm*16 + gg, c0 = wn + tn*8 + 2*tt_;
            S[(m0    )*132 + c0    ] = acc[tm][tn][0];
            S[(m0    )*132 + c0 + 1] = acc[tm][tn][1];
            S[(m0 + 8)*132 + c0    ] = acc[tm][tn][2];
            S[(m0 + 8)*132 + c0 + 1] = acc[tm][tn][3];
        }
    __syncthreads();

    #pragma unroll
    for (int i = 0; i < 16; i++) {
        int u = tid + i*256;
        int half = u >> 11, k8rel = (u >> 8) & 7, rt = (u >> 5) & 7, l = u & 31;
        int g2 = l >> 2, t2 = l & 3;
        int col = half*64 + k8rel*8 + t2;
        const float* s0 = S + (rt*16 + g2)*132 + col;
        float4 v;
        v.x = rnd_tf32(s0[0]);
        v.y = rnd_tf32(s0[8*132]);
        v.z = rnd_tf32(s0[4]);
        v.w = rnd_tf32(s0[8*132 + 4]);
        size_t dst = (size_t)((n0 + half)*8 + pt)*65536
                   + (size_t)(h*8 + k8rel)*1024 + rt*128 + l*4;
        *(float4*)(g_yp + dst) = v;
    }
}

// ---------------------------------------------------------------------------
// Stage 3: out[m][e] = log_cosh( y @ W + b )
// grid (x: 4 e-tiles of 128, y: 512 m-tiles of 128)
// ---------------------------------------------------------------------------
__global__ __launch_bounds__(256, 2) void k_stage3(const float* __restrict__ bias,
                                                   float* __restrict__ out)
{
    extern __shared__ float sm[];
    const int bn = blockIdx.x * 128;
    const int bm = blockIdx.y * 128;
    float acc[4][4][4] = {};
    const float* b0 = g_wp + (bn >> 3) * 64;
    gemm_loop(g_yp + (size_t)(bm >> 7)*65536, b0, b0 + 512, 4096, 16, sm, acc);

    const int tid = threadIdx.x, wid = tid >> 5, lane = tid & 31;
    const int wm = (wid >> 2) * 64, wn = (wid & 3) * 32;
    const int gg = lane >> 2, tt_ = lane & 3;
    #pragma unroll
    for (int tn = 0; tn < 4; tn++) {
        int n0 = wn + tn*8 + 2*tt_;
        float bb0 = bias[bn + n0], bb1 = bias[bn + n0 + 1];
        #pragma unroll
        for (int tm = 0; tm < 4; tm++) {
            int m0 = bm + wm + tm*16 + gg;
            float2 v0 = make_float2(log_cosh_f(acc[tm][tn][0] + bb0),
                                    log_cosh_f(acc[tm][tn][1] + bb1));
            float2 v1 = make_float2(log_cosh_f(acc[tm][tn][2] + bb0),
                                    log_cosh_f(acc[tm][tn][3] + bb1));
            *(float2*)(out + (size_t)(m0    )*EE_ + bn + n0) = v0;
            *(float2*)(out + (size_t)(m0 + 8)*EE_ + bn + n0) = v1;
        }
    }
}

// ---------------------------------------------------------------------------
// Prep: pack operands into fragment-major layouts (tf32-rounded)
// ---------------------------------------------------------------------------
__global__ void k_pack_x(const float* __restrict__ x)
{
    __shared__ float S[128*36];
    const int panel = blockIdx.x, kslab = blockIdx.y;
    const int tid = threadIdx.x;
    #pragma unroll
    for (int i = 0; i < 4; i++) {
        int c = tid + i*256;           // 1024 x 16B chunks
        int row = c >> 3, seg = c & 7;
        float4 v = *(const float4*)(x + (size_t)(panel*128 + row)*512 + kslab*32 + seg*4);
        *(float4*)(S + row*36 + seg*4) = v;
    }
    __syncthreads();
    #pragma unroll
    for (int i = 0; i < 4; i++) {
        int u = tid + i*256;
        int k8 = u >> 8, rt = (u >> 5) & 7, l = u & 31;
        int g = l >> 2, t = l & 3;
        const float* s = S + (rt*16 + g)*36 + k8*8 + t;
        float4 v;
        v.x = rnd_tf32(s[0]);      v.y = rnd_tf32(s[8*36]);
        v.z = rnd_tf32(s[4]);      v.w = rnd_tf32(s[8*36 + 4]);
        *(float4*)(g_xa + (size_t)panel*65536 + (size_t)(kslab*4 + k8)*1024
                   + rt*128 + l*4) = v;
    }
}

__global__ void k_pack_v(const float* __restrict__ V)
{
    int k8 = blockIdx.x, nb = blockIdx.y*8 + (threadIdx.x >> 5), l = threadIdx.x & 31;
    int g = l >> 2, t = l & 3;
    float2 v;
    v.x = rnd_tf32(V[(size_t)(nb*8 + g)*512 + k8*8 + t]);
    v.y = rnd_tf32(V[(size_t)(nb*8 + g)*512 + k8*8 + t + 4]);
    *(float2*)(g_vp + k8*4096 + nb*64 + l*2) = v;
}

__global__ void k_pack_w(const float* __restrict__ W)   // packs W^T
{
    int k8 = blockIdx.x, nb = blockIdx.y*8 + (threadIdx.x >> 5), l = threadIdx.x & 31;
    int g = l >> 2, t = l & 3;
    float2 v;
    v.x = rnd_tf32(W[(size_t)(k8*8 + t    )*512 + nb*8 + g]);
    v.y = rnd_tf32(W[(size_t)(k8*8 + t + 4)*512 + nb*8 + g]);
    *(float2*)(g_wp + k8*4096 + nb*64 + l*2) = v;
}

__global__ void k_pack_amat(const float* __restrict__ alpha)
{
    __shared__ float as_[1024];
    const int k8c = blockIdx.x, pt = blockIdx.y, h = blockIdx.z;
    const int tid = threadIdx.x;
    for (int i = tid; i < 1024; i += 256) as_[i] = rnd_tf32(alpha[h*1024 + i]);
    __syncthreads();
    #pragma unroll
    for (int i = 0; i < 16; i++) {
        int u = tid + i*256;
        int k8r = u >> 8, rt = (u >> 5) & 7, l = u & 31;
        int g = l >> 2, t = l & 3;
        int j = (k8c*16 + k8r)*8 + t;
        int p = pt*128 + rt*16 + g;
        float4 v;
        v.x = as_[(j - p    ) & 1023];
        v.y = as_[(j - p - 8) & 1023];
        v.z = as_[(j + 4 - p    ) & 1023];
        v.w = as_[(j + 4 - p - 8) & 1023];
        *(float4*)(g_ap + (size_t)(h*8 + pt)*131072
                   + (size_t)(k8c*16 + k8r)*1024 + rt*128 + l*4) = v;
    }
}

// ---------------------------------------------------------------------------
extern "C" void kernel_launch(void* const* d_in, const int* in_sizes, int n_in,
                              void* d_out, int out_size)
{
    const float* x     = (const float*)d_in[0];
    const float* alpha = (const float*)d_in[1];
    const float* V     = (const float*)d_in[2];
    const float* W     = (const float*)d_in[3];
    const float* b     = (const float*)d_in[4];
    float* out = (float*)d_out;

    cudaFuncSetAttribute(k_stage1, cudaFuncAttributeMaxDynamicSharedMemorySize, SMEM_BYTES);
    cudaFuncSetAttribute(k_stage2, cudaFuncAttributeMaxDynamicSharedMemorySize, SMEM_BYTES);
    cudaFuncSetAttribute(k_stage3, cudaFuncAttributeMaxDynamicSharedMemorySize, SMEM_BYTES);

    // Prep: pack all operands to fragment-major tf32 layouts
    k_pack_x   <<<dim3(512, 16), 256>>>(x);
    k_pack_v   <<<dim3(64, 8),   256>>>(V);
    k_pack_w   <<<dim3(64, 8),   256>>>(W);
    k_pack_amat<<<dim3(8, 8, 8), 256>>>(alpha);

    // Stage 1: ws = (x @ V^T), packed-B out     M=65536 N=512 K=512
    k_stage1<<<dim3(4, 512), 256, SMEM_BYTES>>>();
    // Stage 2: y = alpha_mat @ ws, packed-A out M=1024 N=128 K=1024 (x64 batches)
    k_stage2<<<dim3(32, 64), 256, SMEM_BYTES>>>();
    // Stage 3: out = log_cosh(y @ W + b)        M=65536 N=512 K=512
    k_stage3<<<dim3(4, 512), 256, SMEM_BYTES>>>(b, out);
}

// round 7
// speedup vs baseline: 7.0822x; 1.6759x over previous
#include <cuda_runtime.h>
#include <cuda_fp16.h>
#include <cstdint>
#include <math.h>

#define NN_ 64
#define PP_ 1024
#define EE_ 512
#define HH_ 8
#define MBIG (NN_*PP_)   // 65536

// dynamic smem: 3 stages x (A 8192 + B 8192 halfs) = 49152 halfs = 98304 B
#define SMEM_BYTES 98304

// ---------------- scratch (__device__ globals; no allocs allowed) ----------
// Packed-A (fp16), per 128-row panel: [K/16][8 rt][32 lane][8 halfs]
//   lane(g=l>>2,t=l&3): {A[rt*16+g][16k+2t],[+1], A[+8 row][2t],[+1], A[g][2t+8],[+9], A[g+8][2t+8],[+9]}
// Packed-B (fp16): [K/16][nb][32 lane][4 halfs]: {B[nb*8+g][16k+2t],[+1],[2t+8],[+9]}
__device__ __half g_xa [(size_t)512*65536];   // x packed-A, 512 panels        64MB
__device__ __half g_vp [(size_t)EE_*EE_];     // V packed-B  [32 k16][64 nb]   0.5MB
__device__ __half g_wp [(size_t)EE_*EE_];     // W^T packed-B                  0.5MB
__device__ __half g_ap [(size_t)64*131072];   // alpha_mat packed-A, 64 panels 16MB
__device__ __half g_wsp[(size_t)512*65536];   // ws packed-B per (n,h) slab    64MB
__device__ __half g_yp [(size_t)512*65536];   // y packed-A, 512 panels        64MB

// ---------------- helpers --------------------------------------------------
__device__ __forceinline__ uint32_t smem_u32(const void* p){
    uint32_t a;
    asm("{ .reg .u64 t; cvta.to.shared.u64 t, %1; cvt.u32.u64 %0, t; }":"=r"(a):"l"(p));
    return a;
}
__device__ __forceinline__ uint32_t f2h2(float a, float b){
    __half2 h = __floats2half2_rn(a, b);
    return *(uint32_t*)&h;
}
__device__ __forceinline__ float log_cosh_f(float v){
    float ax = fabsf(v);
    return ax + log1pf(expf(-2.0f*ax)) - 0.6931471805599453f;
}
__device__ __forceinline__ void mma_f16(float c[4], uint4 a, uint2 b)
{
    asm volatile("mma.sync.aligned.m16n8k16.row.col.f32.f16.f16.f32 "
        "{%0,%1,%2,%3}, {%4,%5,%6,%7}, {%8,%9}, {%0,%1,%2,%3};"
        : "+f"(c[0]), "+f"(c[1]), "+f"(c[2]), "+f"(c[3])
        : "r"(a.x), "r"(a.y), "r"(a.z), "r"(a.w), "r"(b.x), "r"(b.y));
}

// ---------------------------------------------------------------------------
// Mainloop: acc(128x128) += A(128xK) * B(128xK)^T, fp16 fragment-major packed.
// Tile BK=64 (4 k16 steps). 3-stage cp.async pipeline, one sync per tile.
// 256 thr, warps 2(M)x4(N), warp tile 64x32. 64 MMAs + 32 LDS per warp-tile.
// A slab/tile: 8192 halfs contiguous at Ap + tt*8192.
// B per k16: nb 0..7 from B0, 8..15 from B1; per-k16 stride bstride (halfs).
// ---------------------------------------------------------------------------
__device__ __forceinline__ void gemm_loop(
    const __half* __restrict__ Ap,
    const __half* __restrict__ B0, const __half* __restrict__ B1,
    size_t bstride, int kt, __half* __restrict__ sm, float acc[4][4][4])
{
    const int tid = threadIdx.x, wid = tid >> 5, lane = tid & 31;
    const int wrt = (wid >> 2) * 4;   // A rt base: 0 or 4
    const int wnb = (wid & 3) * 4;    // B nb base: 0,4,8,12

    auto load_tile = [&](int tt, int buf){
        __half* dA = sm + buf*16384;
        __half* dB = dA + 8192;
        const __half* As = Ap + (size_t)tt*8192;
        #pragma unroll
        for (int i = 0; i < 4; i++) {                 // A: 1024 x 16B chunks
            int c = tid + i*256;
            uint32_t dst = smem_u32(dA + c*8);
            asm volatile("cp.async.cg.shared.global [%0], [%1], 16;"
                         :: "r"(dst), "l"(As + c*8));
        }
        #pragma unroll
        for (int i = 0; i < 4; i++) {                 // B: 1024 x 16B chunks
            int c = tid + i*256;
            int k16s = c >> 8, r = c & 255;
            int nb = r >> 4, lp = r & 15;
            const __half* src = ((nb & 8) ? B1 : B0)
                              + (size_t)(tt*4 + k16s)*bstride + (nb & 7)*128 + lp*8;
            uint32_t dst = smem_u32(dB + k16s*2048 + nb*128 + lp*8);
            asm volatile("cp.async.cg.shared.global [%0], [%1], 16;"
                         :: "r"(dst), "l"(src));
        }
        asm volatile("cp.async.commit_group;" ::: "memory");
    };

    load_tile(0, 0);
    if (kt > 1) load_tile(1, 1);

    for (int tt = 0; tt < kt; tt++) {
        const int cur = tt % 3;
        asm volatile("cp.async.wait_group 1;" ::: "memory");
        __syncthreads();
        if (tt + 2 < kt) load_tile(tt + 2, (tt + 2) % 3);

        const uint4* fA = (const uint4*)(sm + cur*16384);
        const uint2* fB = (const uint2*)(sm + cur*16384 + 8192);
        #pragma unroll
        for (int ks = 0; ks < 4; ks++) {
            uint4 a[4]; uint2 b[4];
            #pragma unroll
            for (int tm = 0; tm < 4; tm++)
                a[tm] = fA[ks*256 + (wrt + tm)*32 + lane];
            #pragma unroll
            for (int tn = 0; tn < 4; tn++)
                b[tn] = fB[ks*512 + (wnb + tn)*32 + lane];
            #pragma unroll
            for (int tm = 0; tm < 4; tm++)
                #pragma unroll
                for (int tn = 0; tn < 4; tn++)
                    mma_f16(acc[tm][tn], a[tm], b[tn]);
        }
    }
}

// ---------------------------------------------------------------------------
// Stage 1: ws[n,p,hr] = x @ V^T; epilogue writes packed-B fp16 slabs g_wsp.
// grid (x: 4 hr-tiles of 128, y: 512 m-tiles of 128)
// ---------------------------------------------------------------------------
__global__ __launch_bounds__(256, 2) void k_stage1()
{
    extern __shared__ __half smh[];
    const int bn = blockIdx.x * 128;
    const int bm = blockIdx.y * 128;
    float acc[4][4][4] = {};
    const __half* b0 = g_vp + (bn >> 3) * 128;
    gemm_loop(g_xa + (size_t)(bm >> 7)*65536, b0, b0 + 1024, 8192, 8, smh, acc);

    __syncthreads();
    float* Ts = (float*)smh;   // Ts[hrloc][ploc], stride 132 (transposed C)
    const int tid = threadIdx.x, wid = tid >> 5, lane = tid & 31;
    const int wm = (wid >> 2) * 64, wn = (wid & 3) * 32;
    const int gg = lane >> 2, tq = lane & 3;
    #pragma unroll
    for (int tm = 0; tm < 4; tm++)
        #pragma unroll
        for (int tn = 0; tn < 4; tn++) {
            int m0 = wm + tm*16 + gg, n0 = wn + tn*8 + 2*tq;
            Ts[(n0    )*132 + m0    ] = acc[tm][tn][0];
            Ts[(n0 + 1)*132 + m0    ] = acc[tm][tn][1];
            Ts[(n0    )*132 + m0 + 8] = acc[tm][tn][2];
            Ts[(n0 + 1)*132 + m0 + 8] = acc[tm][tn][3];
        }
    __syncthreads();

    const int n = bm >> 10, pbase = bm & 1023;
    #pragma unroll
    for (int i = 0; i < 16; i++) {
        int u = tid + i*256;
        int k16rel = u >> 9, rest = u & 511;
        int nbg = rest >> 5, l = rest & 31;
        int g = l >> 2, t = l & 3;
        int hrloc = nbg*8 + g;
        int hrAbs = bn + hrloc;
        const float* ts = Ts + hrloc*132 + k16rel*16 + 2*t;
        uint2 v;
        v.x = f2h2(ts[0], ts[1]);
        v.y = f2h2(ts[8], ts[9]);
        size_t dst = (size_t)(n*8 + (hrAbs >> 6))*65536
                   + (size_t)((pbase >> 4) + k16rel)*1024
                   + ((hrAbs >> 3) & 7)*128 + l*4;
        *(uint2*)(g_wsp + dst) = v;
    }
}

// ---------------------------------------------------------------------------
// Stage 2: y[n,p,h*64+r] = alpha_mat @ ws; epilogue writes packed-A fp16 g_yp.
// Two n per block (B halves). grid (x: 32 n-pairs, y: h*8 + ptile)
// ---------------------------------------------------------------------------
__global__ __launch_bounds__(256, 2) void k_stage2()
{
    extern __shared__ __half smh[];
    const int n0 = blockIdx.x * 2;
    const int h  = blockIdx.y >> 3;
    const int pt = blockIdx.y & 7;
    float acc[4][4][4] = {};
    gemm_loop(g_ap + (size_t)(h*8 + pt)*131072,
              g_wsp + (size_t)(n0*8 + h)*65536,
              g_wsp + (size_t)((n0+1)*8 + h)*65536,
              1024, 16, smh, acc);

    __syncthreads();
    float* S = (float*)smh;   // S[ploc][col], stride 132; col = half*64 + r
    const int tid = threadIdx.x, wid = tid >> 5, lane = tid & 31;
    const int wm = (wid >> 2) * 64, wn = (wid & 3) * 32;
    const int gg = lane >> 2, tq = lane & 3;
    #pragma unroll
    for (int tm = 0; tm < 4; tm++)
        #pragma unroll
        for (int tn = 0; tn < 4; tn++) {
            int m0 = wm + tm*16 + gg, c0 = wn + tn*8 + 2*tq;
            S[(m0    )*132 + c0    ] = acc[tm][tn][0];
            S[(m0    )*132 + c0 + 1] = acc[tm][tn][1];
            S[(m0 + 8)*132 + c0    ] = acc[tm][tn][2];
            S[(m0 + 8)*132 + c0 + 1] = acc[tm][tn][3];
        }
    __syncthreads();

    #pragma unroll
    for (int i = 0; i < 8; i++) {
        int u = tid + i*256;
        int half_ = u >> 10, v_ = u & 1023;
        int k16rel = v_ >> 8, rt = (v_ >> 5) & 7, l = v_ & 31;
        int g = l >> 2, t = l & 3;
        int row0 = rt*16 + g;
        const float* s0 = S + row0*132 + half_*64 + k16rel*16 + 2*t;
        const float* s1 = s0 + 8*132;
        uint4 v;
        v.x = f2h2(s0[0], s0[1]);
        v.y = f2h2(s1[0], s1[1]);
        v.z = f2h2(s0[8], s0[9]);
        v.w = f2h2(s1[8], s1[9]);
        size_t dst = (size_t)((n0 + half_)*8 + pt)*65536
                   + (size_t)(h*4 + k16rel)*2048 + rt*256 + l*8;
        *(uint4*)(g_yp + dst) = v;
    }
}

// ---------------------------------------------------------------------------
// Stage 3: out[m][e] = log_cosh( y @ W + b )
// grid (x: 4 e-tiles of 128, y: 512 m-tiles of 128)
// ---------------------------------------------------------------------------
__global__ __launch_bounds__(256, 2) void k_stage3(const float* __restrict__ bias,
                                                   float* __restrict__ out)
{
    extern __shared__ __half smh[];
    const int bn = blockIdx.x * 128;
    const int bm = blockIdx.y * 128;
    float acc[4][4][4] = {};
    const __half* b0 = g_wp + (bn >> 3) * 128;
    gemm_loop(g_yp + (size_t)(bm >> 7)*65536, b0, b0 + 1024, 8192, 8, smh, acc);

    const int tid = threadIdx.x, wid = tid >> 5, lane = tid & 31;
    const int wm = (wid >> 2) * 64, wn = (wid & 3) * 32;
    const int gg = lane >> 2, tq = lane & 3;
    #pragma unroll
    for (int tn = 0; tn < 4; tn++) {
        int n0 = wn + tn*8 + 2*tq;
        float bb0 = bias[bn + n0], bb1 = bias[bn + n0 + 1];
        #pragma unroll
        for (int tm = 0; tm < 4; tm++) {
            int m0 = bm + wm + tm*16 + gg;
            float2 v0 = make_float2(log_cosh_f(acc[tm][tn][0] + bb0),
                                    log_cosh_f(acc[tm][tn][1] + bb1));
            float2 v1 = make_float2(log_cosh_f(acc[tm][tn][2] + bb0),
                                    log_cosh_f(acc[tm][tn][3] + bb1));
            *(float2*)(out + (size_t)(m0    )*EE_ + bn + n0) = v0;
            *(float2*)(out + (size_t)(m0 + 8)*EE_ + bn + n0) = v1;
        }
    }
}

// ---------------------------------------------------------------------------
// Prep: pack operands into fp16 fragment-major layouts
// ---------------------------------------------------------------------------
__global__ void k_pack_x(const float* __restrict__ x)   // grid (512 panels, 8 kslabs)
{
    __shared__ float S[128*68];
    const int panel = blockIdx.x, kslab = blockIdx.y;   // kslab covers 64 cols (4 k16)
    const int tid = threadIdx.x;
    #pragma unroll
    for (int i = 0; i < 8; i++) {
        int c = tid + i*256;               // 2048 x 16B chunks
        int row = c >> 4, seg = c & 15;
        float4 v = *(const float4*)(x + (size_t)(panel*128 + row)*512 + kslab*64 + seg*4);
        *(float4*)(S + row*68 + seg*4) = v;
    }
    __syncthreads();
    #pragma unroll
    for (int i = 0; i < 4; i++) {
        int u = tid + i*256;
        int k16 = u >> 8, rt = (u >> 5) & 7, l = u & 31;
        int g = l >> 2, t = l & 3;
        const float* s0 = S + (rt*16 + g)*68 + k16*16 + 2*t;
        const float* s1 = s0 + 8*68;
        uint4 v;
        v.x = f2h2(s0[0], s0[1]);
        v.y = f2h2(s1[0], s1[1]);
        v.z = f2h2(s0[8], s0[9]);
        v.w = f2h2(s1[8], s1[9]);
        *(uint4*)(g_xa + (size_t)panel*65536 + (size_t)(kslab*4 + k16)*2048
                  + rt*256 + l*8) = v;
    }
}

__global__ void k_pack_v(const float* __restrict__ V)   // grid (32 k16, 8)
{
    int k16 = blockIdx.x, nb = blockIdx.y*8 + (threadIdx.x >> 5), l = threadIdx.x & 31;
    int g = l >> 2, t = l & 3;
    const float* r = V + (size_t)(nb*8 + g)*512 + k16*16 + 2*t;
    uint2 v;
    v.x = f2h2(r[0], r[1]);
    v.y = f2h2(r[8], r[9]);
    *(uint2*)(g_vp + k16*8192 + nb*128 + l*4) = v;
}

__global__ void k_pack_w(const float* __restrict__ W)   // packs W^T; grid (32, 8)
{
    int k16 = blockIdx.x, nb = blockIdx.y*8 + (threadIdx.x >> 5), l = threadIdx.x & 31;
    int g = l >> 2, t = l & 3;
    int e = nb*8 + g, k = k16*16 + 2*t;
    uint2 v;
    v.x = f2h2(W[(size_t)(k    )*512 + e], W[(size_t)(k + 1)*512 + e]);
    v.y = f2h2(W[(size_t)(k + 8)*512 + e], W[(size_t)(k + 9)*512 + e]);
    *(uint2*)(g_wp + k16*8192 + nb*128 + l*4) = v;
}

__global__ void k_pack_amat(const float* __restrict__ alpha)  // grid (8 k16c, 8 pt, 8 h)
{
    __shared__ float as_[1024];
    const int k16c = blockIdx.x, pt = blockIdx.y, h = blockIdx.z;
    const int tid = threadIdx.x;
    for (int i = tid; i < 1024; i += 256) as_[i] = alpha[h*1024 + i];
    __syncthreads();
    #pragma unroll
    for (int i = 0; i < 8; i++) {
        int u = tid + i*256;
        int k16r = u >> 8, rt = (u >> 5) & 7, l = u & 31;
        int g = l >> 2, t = l & 3;
        int j = (k16c*8 + k16r)*16 + 2*t;
        int p = pt*128 + rt*16 + g;
        uint4 v;
        v.x = f2h2(as_[(j     - p) & 1023], as_[(j + 1 - p) & 1023]);
        v.y = f2h2(as_[(j - 8 - p) & 1023], as_[(j - 7 - p) & 1023]);
        v.z = f2h2(as_[(j + 8 - p) & 1023], as_[(j + 9 - p) & 1023]);
        v.w = f2h2(as_[(j     - p) & 1023], as_[(j + 1 - p) & 1023]);
        // a1/a3 are rows p+8: alpha[(j - (p+8))] etc.
        v.w = f2h2(as_[(j + 8 - p - 8) & 1023], as_[(j + 9 - p - 8) & 1023]);
        *(uint4*)(g_ap + (size_t)(h*8 + pt)*131072
                  + (size_t)(k16c*8 + k16r)*2048 + rt*256 + l*8) = v;
    }
}

// ---------------------------------------------------------------------------
extern "C" void kernel_launch(void* const* d_in, const int* in_sizes, int n_in,
                              void* d_out, int out_size)
{
    const float* x     = (const float*)d_in[0];
    const float* alpha = (const float*)d_in[1];
    const float* V     = (const float*)d_in[2];
    const float* W     = (const float*)d_in[3];
    const float* b     = (const float*)d_in[4];
    float* out = (float*)d_out;

    cudaFuncSetAttribute(k_stage1, cudaFuncAttributeMaxDynamicSharedMemorySize, SMEM_BYTES);
    cudaFuncSetAttribute(k_stage2, cudaFuncAttributeMaxDynamicSharedMemorySize, SMEM_BYTES);
    cudaFuncSetAttribute(k_stage3, cudaFuncAttributeMaxDynamicSharedMemorySize, SMEM_BYTES);

    // Prep: pack all operands to fragment-major fp16 layouts
    k_pack_x   <<<dim3(512, 8), 256>>>(x);
    k_pack_v   <<<dim3(32, 8),  256>>>(V);
    k_pack_w   <<<dim3(32, 8),  256>>>(W);
    k_pack_amat<<<dim3(8, 8, 8), 256>>>(alpha);

    // Stage 1: ws = (x @ V^T), packed-B out     M=65536 N=512 K=512
    k_stage1<<<dim3(4, 512), 256, SMEM_BYTES>>>();
    // Stage 2: y = alpha_mat @ ws, packed-A out M=1024 N=128 K=1024 (x64 batches)
    k_stage2<<<dim3(32, 64), 256, SMEM_BYTES>>>();
    // Stage 3: out = log_cosh(y @ W + b)        M=65536 N=512 K=512
    k_stage3<<<dim3(4, 512), 256, SMEM_BYTES>>>(b, out);
}